// round 9
// baseline (speedup 1.0000x reference)
#include <cuda_runtime.h>
#include <cuda_bf16.h>
#include <cfloat>
#include <cstdint>

// ResidualVectorQuantizer, exact argmin via bf16-MMA prefilter + scalar verify.
// B=16,E=64,H=64,W=64 -> N=65536 tokens; K=1024, NC=8 stages.
//
// Exact reference numerics (validated rel_err==0 in rounds 1-6, 8):
//   r2  = sequential sum of rounded squares of res (e ascending)
//   dot = sequential fused-FMA over e ascending
//   d   = fl(fl(r2 - fl(2*dot)) + cb2), argmin first-index tie-break
//   res -= q elementwise rounded; quant = ((q0+q1)+...)+q7
//
// Prefilter: bf16 m16n8k16 MMA scores t~ = fl(cb2 - 2*dot~) (fp32), reduced
// in registers to per-8k-block minima; only bm[tok][block] hits smem. Every
// k in any block with blockmin <= min + MARGIN is verified exactly.
// Guarantee: block of true argmin k* has blockmin <= t~(k*) <= t~min + 2eps.
//
// R9 = R6 MMA structure + R8 block-min pipeline:
//  - 16 warps = 8 n-slices x 2 m-halves (2 m-tiles/warp): 32 B-LDS per 64
//    MMAs per gtile (R8's shape was 64:32 — 4x worse).
//  - __launch_bounds__(512,1): 128 regs, no spills (R8's (512,2) forced
//    <=64 regs and spilled the verify loop).
//  - block-min epilogue in registers, 33KB fp32 bm (no 132KB fp16 scores,
//    no full rescan), CAPB=64 (R8-validated capacity).

#define NTOK   65536
#define EDIM   64
#define KCB    1024
#define NCODE  8
#define MTOK   64          // tokens per CTA
#define TPB    512
#define NWARP  16
#define GTW    256         // codebook k-gtile width (codewords)
#define BPITCH 264         // B tile pitch in 32-bit words: conflict-free
#define RPITCH 68          // res row pitch (floats)
#define BMP    132         // block-min row pitch (floats), 128 blocks + pad
#define CAPB   64          // candidate blocks per warp (4 tokens)
#define MARGIN 2e-3f

// packed bf16 pairs along e: word(e2,k) = {lo=cb[k][2e2], hi=cb[k][2e2+1]}
__device__ unsigned g_cbt[NCODE * (EDIM/2) * KCB];
__device__ float    g_cb2[NCODE * KCB];         // exact ||cb||^2

__device__ __forceinline__ unsigned packbf(float lo, float hi) {
    unsigned r;
    asm("cvt.rn.bf16x2.f32 %0, %1, %2;" : "=r"(r) : "f"(hi), "f"(lo));
    return r;
}

__device__ __forceinline__ void mma_bf16(float& c0, float& c1, float& c2, float& c3,
                                         unsigned a0, unsigned a1, unsigned a2, unsigned a3,
                                         unsigned b0, unsigned b1) {
    asm volatile(
        "mma.sync.aligned.m16n8k16.row.col.f32.bf16.bf16.f32 "
        "{%0,%1,%2,%3}, {%4,%5,%6,%7}, {%8,%9}, {%0,%1,%2,%3};\n"
        : "+f"(c0), "+f"(c1), "+f"(c2), "+f"(c3)
        : "r"(a0), "r"(a1), "r"(a2), "r"(a3), "r"(b0), "r"(b1));
}

// ---- precompute: exact cb2 ----
__global__ void cb2_kernel(const float* __restrict__ cb)
{
    const int i = blockIdx.x * blockDim.x + threadIdx.x;   // 0..8191
    const float* row = cb + (size_t)i * EDIM;
    float c2 = 0.0f;
#pragma unroll
    for (int e = 0; e < EDIM; e++)
        c2 = __fadd_rn(c2, __fmul_rn(row[e], row[e]));
    g_cb2[i] = c2;
}

// ---- precompute: transpose + bf16-pack codebook to [s][e2][k] ----
__global__ void cbt_kernel(const float* __restrict__ cb)
{
    __shared__ float tile[32][33];       // [n_local][e_local]
    const int s  = blockIdx.z;
    const int n0 = blockIdx.x * 32;
    const int e0 = blockIdx.y * 32;
    const int tx = threadIdx.x, ty = threadIdx.y;
#pragma unroll
    for (int i = 0; i < 32; i += 8)
        tile[ty + i][tx] = cb[((size_t)s * KCB + (n0 + ty + i)) * EDIM + e0 + tx];
    __syncthreads();
#pragma unroll
    for (int i = 0; i < 2; i++) {
        int e2l = ty + i * 8;
        unsigned wv = packbf(tile[tx][2*e2l], tile[tx][2*e2l + 1]);
        g_cbt[((size_t)s * (EDIM/2) + (e0/2 + e2l)) * KCB + n0 + tx] = wv;
    }
}

struct Cand {
    int cnt;
    int pad[3];
    int tok[CAPB];            // local token 0..3
    int bk[CAPB];             // block index 0..127
};

// smem segment sizes (bytes)
#define BM_BYTES   (MTOK * BMP * 4)            // 33792
#define BS_BYTES   ((EDIM/2) * BPITCH * 4)     // 33792
#define RES_BYTES  (MTOK * RPITCH * 4)         // 17408
#define C2S_BYTES  (GTW * 4)                   // 1024
#define CAND_BYTES (NWARP * (int)sizeof(Cand)) // 8448
#define R2S_BYTES  (MTOK * 4)
#define SEL_BYTES  (MTOK * 4)
#define HIST_BYTES (NCODE * MTOK * 4)
#define SMEM_BYTES (BM_BYTES + BS_BYTES + RES_BYTES + C2S_BYTES + CAND_BYTES + \
                    R2S_BYTES + SEL_BYTES + HIST_BYTES)

__global__ __launch_bounds__(TPB, 1)
void rvq_kernel(const float* __restrict__ emb,
                const float* __restrict__ cb,
                float* __restrict__ out)
{
    extern __shared__ char smem[];
    float*    bm   = (float*)smem;                         // [64][BMP]
    unsigned* bsw  = (unsigned*)(smem + BM_BYTES);         // [32][BPITCH]
    float*    res  = (float*)(smem + BM_BYTES + BS_BYTES); // [64][RPITCH]
    float*    c2s  = (float*)(smem + BM_BYTES + BS_BYTES + RES_BYTES);
    Cand*     cands= (Cand*)(smem + BM_BYTES + BS_BYTES + RES_BYTES + C2S_BYTES);
    float*    r2s  = (float*)((char*)cands + CAND_BYTES);
    int*      sel  = (int*)((char*)r2s + R2S_BYTES);
    int*      hist = (int*)((char*)sel + SEL_BYTES);       // [s][tok]

    const int tid  = threadIdx.x;
    const int w    = tid >> 5;      // 0..15
    const int lane = tid & 31;
    const int qr   = lane >> 2;     // 0..7
    const int qc   = lane & 3;      // 0..3
    const int nw   = w & 7;         // n-slice (32 wide)
    const int mh   = w >> 3;        // m-half: m-tiles {2mh, 2mh+1}

    // ---- init: load embeddings into res smem ----
    {
        const int tok = tid & 63;
        const int ec  = tid >> 6;       // 0..7
        const int n   = blockIdx.x * MTOK + tok;
        const int b   = n >> 12;
        const int hw  = n & 4095;
        const float* ep = emb + (size_t)b * (EDIM * 4096) + hw;
#pragma unroll
        for (int j = 0; j < 8; j++) {
            int e = ec * 8 + j;
            res[tok * RPITCH + e] = ep[(size_t)e * 4096];
        }
    }
    __syncthreads();

#pragma unroll 1
    for (int s = 0; s < NCODE; s++) {
        // ---- A fragments: this warp's 2 m-tiles, bf16 packed (32 regs) ----
        unsigned a[2][16];
#pragma unroll
        for (int mtl = 0; mtl < 2; mtl++) {
            int r0 = (mh * 2 + mtl) * 16 + qr;
            const float* p0 = res + (size_t)r0 * RPITCH;
            const float* p1 = p0 + 8 * RPITCH;
#pragma unroll
            for (int ks = 0; ks < 4; ks++) {
                int c = 16 * ks + 2 * qc;
                a[mtl][ks*4+0] = packbf(p0[c],   p0[c+1]);
                a[mtl][ks*4+1] = packbf(p1[c],   p1[c+1]);
                a[mtl][ks*4+2] = packbf(p0[c+8], p0[c+9]);
                a[mtl][ks*4+3] = packbf(p1[c+8], p1[c+9]);
            }
        }
        // ---- exact r2 per token (sequential, e ascending) ----
        if (tid < MTOK) {
            const float* rr = res + tid * RPITCH;
            float r2 = 0.0f;
#pragma unroll
            for (int e = 0; e < EDIM; e++)
                r2 = __fadd_rn(r2, __fmul_rn(rr[e], rr[e]));
            r2s[tid] = r2;
        }

        // ---- score pass over K in 4 gtiles of 256 ----
#pragma unroll 1
        for (int gt = 0; gt < 4; gt++) {
            __syncthreads();
            // load packed B gtile into [e2][BPITCH]
            const unsigned* gsrc = g_cbt + ((size_t)s * (EDIM/2)) * KCB + gt * GTW;
#pragma unroll
            for (int j = 0; j < 4; j++) {
                int idx = j * TPB + tid;       // 0..2047
                int e2  = idx >> 6;            // 0..31
                int c4  = idx & 63;
                uint4 v = __ldg((const uint4*)(gsrc + (size_t)e2 * KCB) + c4);
                *(uint4*)(bsw + e2 * BPITCH + c4 * 4) = v;
            }
            if (tid < GTW)
                c2s[tid] = __ldg(g_cb2 + s * KCB + gt * GTW + tid);
            __syncthreads();

            // this warp's 32-wide n-slice, two 16-wide passes, 2 m-tiles
            const int nbase = nw * 32;
#pragma unroll 1
            for (int np = 0; np < 2; np++) {
                const int n0 = nbase + np * 16;
                float acc[2][8];
#pragma unroll
                for (int mtl = 0; mtl < 2; mtl++)
#pragma unroll
                    for (int j = 0; j < 8; j++) acc[mtl][j] = 0.0f;

                const unsigned* bp = bsw + n0 + qr;
#pragma unroll
                for (int ks = 0; ks < 4; ks++) {
                    // conflict-free: bank = 8*qc + qr  (264 % 32 == 8)
                    unsigned b00 = bp[(ks*8     + qc) * BPITCH];
                    unsigned b01 = bp[(ks*8 + 4 + qc) * BPITCH];
                    unsigned b10 = bp[(ks*8     + qc) * BPITCH + 8];
                    unsigned b11 = bp[(ks*8 + 4 + qc) * BPITCH + 8];
#pragma unroll
                    for (int mtl = 0; mtl < 2; mtl++) {
                        mma_bf16(acc[mtl][0], acc[mtl][1], acc[mtl][2], acc[mtl][3],
                                 a[mtl][ks*4], a[mtl][ks*4+1], a[mtl][ks*4+2], a[mtl][ks*4+3],
                                 b00, b01);
                        mma_bf16(acc[mtl][4], acc[mtl][5], acc[mtl][6], acc[mtl][7],
                                 a[mtl][ks*4], a[mtl][ks*4+1], a[mtl][ks*4+2], a[mtl][ks*4+3],
                                 b10, b11);
                    }
                }
                // epilogue: t = fl(cb2 - 2*dot), reduce to 8-k block minima
                const int cc0 = n0 + 2*qc;
                const int cc1 = cc0 + 8;
                float2 z0 = *(const float2*)(c2s + cc0);
                float2 z1 = *(const float2*)(c2s + cc1);
                const int blk = (gt * GTW + n0) >> 3;   // global block idx
#pragma unroll
                for (int mtl = 0; mtl < 2; mtl++) {
                    float t0 = fmaf(-2.f, acc[mtl][0], z0.x);
                    float t1 = fmaf(-2.f, acc[mtl][1], z0.y);
                    float t2 = fmaf(-2.f, acc[mtl][2], z0.x);
                    float t3 = fmaf(-2.f, acc[mtl][3], z0.y);
                    float t4 = fmaf(-2.f, acc[mtl][4], z1.x);
                    float t5 = fmaf(-2.f, acc[mtl][5], z1.y);
                    float t6 = fmaf(-2.f, acc[mtl][6], z1.x);
                    float t7 = fmaf(-2.f, acc[mtl][7], z1.y);
                    // per-quad block minima: rows r0/r0+8, blocks blk, blk+1
                    float m00 = fminf(t0, t1);   // row r0,   block blk
                    float m01 = fminf(t4, t5);   // row r0,   block blk+1
                    float m10 = fminf(t2, t3);   // row r0+8, block blk
                    float m11 = fminf(t6, t7);   // row r0+8, block blk+1
#pragma unroll
                    for (int off = 1; off <= 2; off <<= 1) {
                        m00 = fminf(m00, __shfl_xor_sync(0xffffffffu, m00, off));
                        m01 = fminf(m01, __shfl_xor_sync(0xffffffffu, m01, off));
                        m10 = fminf(m10, __shfl_xor_sync(0xffffffffu, m10, off));
                        m11 = fminf(m11, __shfl_xor_sync(0xffffffffu, m11, off));
                    }
                    if (qc == 0) {
                        const int r0 = (mh * 2 + mtl) * 16 + qr;
                        *(float2*)(bm + (r0    ) * BMP + blk) = make_float2(m00, m01);
                        *(float2*)(bm + (r0 + 8) * BMP + blk) = make_float2(m10, m11);
                    }
                }
            }
        }
        __syncthreads();   // block minima complete

        // ---- per-warp candidate blocks: tokens w*4 .. w*4+3 ----
        Cand* cd = cands + w;
        if (lane == 0) cd->cnt = 0;
        __syncwarp();
        const int tbase = w * 4;
#pragma unroll 1
        for (int t4 = 0; t4 < 4; t4++) {
            const float* brow = bm + (size_t)(tbase + t4) * BMP;
            float4 v = *(const float4*)(brow + lane * 4);
            float lmin = fminf(fminf(v.x, v.y), fminf(v.z, v.w));
#pragma unroll
            for (int off = 16; off; off >>= 1)
                lmin = fminf(lmin, __shfl_xor_sync(0xffffffffu, lmin, off));
            const float thr = lmin + MARGIN;
            if (v.x <= thr) { int p = atomicAdd(&cd->cnt, 1);
                              if (p < CAPB) { cd->tok[p] = t4; cd->bk[p] = lane*4 + 0; } }
            if (v.y <= thr) { int p = atomicAdd(&cd->cnt, 1);
                              if (p < CAPB) { cd->tok[p] = t4; cd->bk[p] = lane*4 + 1; } }
            if (v.z <= thr) { int p = atomicAdd(&cd->cnt, 1);
                              if (p < CAPB) { cd->tok[p] = t4; cd->bk[p] = lane*4 + 2; } }
            if (v.w <= thr) { int p = atomicAdd(&cd->cnt, 1);
                              if (p < CAPB) { cd->tok[p] = t4; cd->bk[p] = lane*4 + 3; } }
        }
        __syncwarp();
        const int ncand = min(cd->cnt, CAPB);
        const int nk = ncand * 8;

        // ---- exact evaluation, folded directly into per-token bests ----
        float bd0 = FLT_MAX, bd1 = FLT_MAX, bd2 = FLT_MAX, bd3 = FLT_MAX;
        int   bk0 = KCB,     bk1 = KCB,     bk2 = KCB,     bk3 = KCB;
        for (int base = 0; base < nk; base += 32) {
            int i = base + lane;
            if (i < nk) {
                int ci = i >> 3;
                int t4 = cd->tok[ci];
                int k  = cd->bk[ci] * 8 + (i & 7);
                int tok = tbase + t4;
                const float4* q4 = (const float4*)(cb + ((size_t)(s * KCB + k)) * EDIM);
                const float* rr = res + tok * RPITCH;
                float dot = 0.0f;
#pragma unroll
                for (int ii = 0; ii < 16; ii++) {
                    float4 q = __ldg(q4 + ii);
                    dot = __fmaf_rn(rr[4*ii+0], q.x, dot);
                    dot = __fmaf_rn(rr[4*ii+1], q.y, dot);
                    dot = __fmaf_rn(rr[4*ii+2], q.z, dot);
                    dot = __fmaf_rn(rr[4*ii+3], q.w, dot);
                }
                float cb2 = __ldg(g_cb2 + s * KCB + k);
                float d = __fadd_rn(__fsub_rn(r2s[tok], __fmul_rn(2.0f, dot)), cb2);
                if (t4 == 0)      { if (d < bd0 || (d == bd0 && k < bk0)) { bd0 = d; bk0 = k; } }
                else if (t4 == 1) { if (d < bd1 || (d == bd1 && k < bk1)) { bd1 = d; bk1 = k; } }
                else if (t4 == 2) { if (d < bd2 || (d == bd2 && k < bk2)) { bd2 = d; bk2 = k; } }
                else              { if (d < bd3 || (d == bd3 && k < bk3)) { bd3 = d; bk3 = k; } }
            }
        }
        // per-token warp argmin with first-index tie-break
#pragma unroll
        for (int off = 16; off; off >>= 1) {
            float od; int ok;
            od = __shfl_xor_sync(0xffffffffu, bd0, off);
            ok = __shfl_xor_sync(0xffffffffu, bk0, off);
            if (od < bd0 || (od == bd0 && ok < bk0)) { bd0 = od; bk0 = ok; }
            od = __shfl_xor_sync(0xffffffffu, bd1, off);
            ok = __shfl_xor_sync(0xffffffffu, bk1, off);
            if (od < bd1 || (od == bd1 && ok < bk1)) { bd1 = od; bk1 = ok; }
            od = __shfl_xor_sync(0xffffffffu, bd2, off);
            ok = __shfl_xor_sync(0xffffffffu, bk2, off);
            if (od < bd2 || (od == bd2 && ok < bk2)) { bd2 = od; bk2 = ok; }
            od = __shfl_xor_sync(0xffffffffu, bd3, off);
            ok = __shfl_xor_sync(0xffffffffu, bk3, off);
            if (od < bd3 || (od == bd3 && ok < bk3)) { bd3 = od; bk3 = ok; }
        }
        if (lane == 0) {
            sel[tbase + 0] = bk0;
            sel[tbase + 1] = bk1;
            sel[tbase + 2] = bk2;
            sel[tbase + 3] = bk3;
        }
        __syncthreads();

        // ---- residual update (exact) ----
        {
            int tok  = tid >> 3;           // 0..63
            int part = tid & 7;            // 0..7, 8 floats each
            int k    = sel[tok];
            const float4* qp = (const float4*)(cb + ((size_t)(s * KCB + k)) * EDIM) + part * 2;
            float* rr = res + tok * RPITCH + part * 8;
#pragma unroll
            for (int ii = 0; ii < 2; ii++) {
                float4 q  = __ldg(qp + ii);
                float4 rv = *(float4*)(rr + 4*ii);
                rv.x = __fsub_rn(rv.x, q.x);
                rv.y = __fsub_rn(rv.y, q.y);
                rv.z = __fsub_rn(rv.z, q.z);
                rv.w = __fsub_rn(rv.w, q.w);
                *(float4*)(rr + 4*ii) = rv;
            }
            if (part == 0) hist[s * MTOK + tok] = k;
        }
        __syncthreads();
    }

    // ---- final epilogue: quant = ((q0+q1)+q2)...+q7, exact order ----
    {
        const int tok = tid & 63;
        const int ec  = tid >> 6;          // 0..7
        const int e0  = ec * 8;
        const int n   = blockIdx.x * MTOK + tok;
        const int b   = n >> 12;
        const int hw  = n & 4095;

        float4 acc[2];
        {
            int k = hist[0 * MTOK + tok];
            const float4* qp = (const float4*)(cb + ((size_t)(0 * KCB + k)) * EDIM + e0);
#pragma unroll
            for (int ii = 0; ii < 2; ii++) acc[ii] = __ldg(qp + ii);
        }
#pragma unroll
        for (int s = 1; s < NCODE; s++) {
            int k = hist[s * MTOK + tok];
            const float4* qp = (const float4*)(cb + ((size_t)(s * KCB + k)) * EDIM + e0);
#pragma unroll
            for (int ii = 0; ii < 2; ii++) {
                float4 q = __ldg(qp + ii);
                acc[ii].x = __fadd_rn(acc[ii].x, q.x);
                acc[ii].y = __fadd_rn(acc[ii].y, q.y);
                acc[ii].z = __fadd_rn(acc[ii].z, q.z);
                acc[ii].w = __fadd_rn(acc[ii].w, q.w);
            }
        }
        float* op = out + (size_t)b * (EDIM * 4096) + hw;
#pragma unroll
        for (int ii = 0; ii < 2; ii++) {
            op[(size_t)(e0 + 4*ii + 0) * 4096] = acc[ii].x;
            op[(size_t)(e0 + 4*ii + 1) * 4096] = acc[ii].y;
            op[(size_t)(e0 + 4*ii + 2) * 4096] = acc[ii].z;
            op[(size_t)(e0 + 4*ii + 3) * 4096] = acc[ii].w;
        }
    }
}

extern "C" void kernel_launch(void* const* d_in, const int* in_sizes, int n_in,
                              void* d_out, int out_size)
{
    const float* emb = (const float*)d_in[0];   // [16,64,64,64]
    const float* cb  = (const float*)d_in[1];   // [8,1024,64]
    float* out = (float*)d_out;
    (void)in_sizes; (void)n_in; (void)out_size;

    cudaFuncSetAttribute(rvq_kernel, cudaFuncAttributeMaxDynamicSharedMemorySize,
                         SMEM_BYTES);

    cbt_kernel<<<dim3(32, 2, 8), dim3(32, 8)>>>(cb);
    cb2_kernel<<<(NCODE * KCB) / 256, 256>>>(cb);
    rvq_kernel<<<NTOK / MTOK, TPB, SMEM_BYTES>>>(emb, cb, out);
}

// round 10
// speedup vs baseline: 1.5452x; 1.5452x over previous
#include <cuda_runtime.h>
#include <cuda_fp16.h>
#include <cuda_bf16.h>
#include <cfloat>
#include <cstdint>

// ResidualVectorQuantizer, exact argmin via bf16-MMA prefilter + scalar verify.
// B=16,E=64,H=64,W=64 -> N=65536 tokens; K=1024, NC=8 stages.
//
// Exact reference numerics (validated rel_err==0 in rounds 1-6, 8):
//   r2  = sequential sum of rounded squares of res (e ascending)
//   dot = sequential fused-FMA over e ascending
//   d   = fl(fl(r2 - fl(2*dot)) + cb2), argmin first-index tie-break
//   res -= q elementwise rounded; quant = ((q0+q1)+...)+q7
// MMA computes approximate scores t~ = cb2 - 2*dot~ (bf16 in, f32 acc,
// fp16-stored); every k with t~ <= min + MARGIN=2e-3 is re-verified exactly
// (R6-validated margin >> worst-case bf16+fp16 approx error ~1.05e-3).
//
// R10 = exact R6 pipeline (731us, rel_err 0) re-tiled for 2 CTAs/SM:
//   MTOK 64->32, TPB 512->256, GTW 256->128  => smem 197KB -> ~96KB.
//   8 warps, each: 2 m-tiles x 16-wide n-slice (same 1:1 LDS:MMA ratio,
//   conflict-free BPITCH=136). Per-token numerics byte-identical to R6.
//   Bet: cross-CTA overlap hides the barrier-serialized phases (R8 beat R9
//   solely on occupancy; block-min path abandoned after R9 regression).

#define NTOK   65536
#define EDIM   64
#define KCB    1024
#define NCODE  8
#define MTOK   32          // tokens per CTA
#define TPB    256
#define NWARP  8
#define GTW    128         // codebook k-gtile width (codewords)
#define NGT    (KCB / GTW) // 8 gtiles
#define BPITCH 136         // B tile pitch in 32-bit words (136%32==8: conflict-free)
#define RPITCH 68          // res row pitch (floats)
#define SCP    1032        // score row pitch (halves) (516%32==4: conflict-free STS)
#define CAP    48
#define MARGIN 2e-3f

// packed bf16 pairs along e: word(e2,k) = {lo=cb[k][2e2], hi=cb[k][2e2+1]}
__device__ unsigned g_cbt[NCODE * (EDIM/2) * KCB];
__device__ float    g_cb2[NCODE * KCB];         // exact ||cb||^2

__device__ __forceinline__ unsigned packbf(float lo, float hi) {
    unsigned r;
    asm("cvt.rn.bf16x2.f32 %0, %1, %2;" : "=r"(r) : "f"(hi), "f"(lo));
    return r;
}

__device__ __forceinline__ __half2 u2h2(unsigned u) {
    return *reinterpret_cast<__half2*>(&u);
}

__device__ __forceinline__ void mma_bf16(float& c0, float& c1, float& c2, float& c3,
                                         unsigned a0, unsigned a1, unsigned a2, unsigned a3,
                                         unsigned b0, unsigned b1) {
    asm volatile(
        "mma.sync.aligned.m16n8k16.row.col.f32.bf16.bf16.f32 "
        "{%0,%1,%2,%3}, {%4,%5,%6,%7}, {%8,%9}, {%0,%1,%2,%3};\n"
        : "+f"(c0), "+f"(c1), "+f"(c2), "+f"(c3)
        : "r"(a0), "r"(a1), "r"(a2), "r"(a3), "r"(b0), "r"(b1));
}

// ---- precompute: exact cb2 ----
__global__ void cb2_kernel(const float* __restrict__ cb)
{
    const int i = blockIdx.x * blockDim.x + threadIdx.x;   // 0..8191
    const float* row = cb + (size_t)i * EDIM;
    float c2 = 0.0f;
#pragma unroll
    for (int e = 0; e < EDIM; e++)
        c2 = __fadd_rn(c2, __fmul_rn(row[e], row[e]));
    g_cb2[i] = c2;
}

// ---- precompute: transpose + bf16-pack codebook to [s][e2][k] ----
__global__ void cbt_kernel(const float* __restrict__ cb)
{
    __shared__ float tile[32][33];       // [n_local][e_local]
    const int s  = blockIdx.z;
    const int n0 = blockIdx.x * 32;
    const int e0 = blockIdx.y * 32;
    const int tx = threadIdx.x, ty = threadIdx.y;
#pragma unroll
    for (int i = 0; i < 32; i += 8)
        tile[ty + i][tx] = cb[((size_t)s * KCB + (n0 + ty + i)) * EDIM + e0 + tx];
    __syncthreads();
#pragma unroll
    for (int i = 0; i < 2; i++) {
        int e2l = ty + i * 8;
        unsigned wv = packbf(tile[tx][2*e2l], tile[tx][2*e2l + 1]);
        g_cbt[((size_t)s * (EDIM/2) + (e0/2 + e2l)) * KCB + n0 + tx] = wv;
    }
}

struct Cand {
    int   cnt;
    int   pad[3];
    int   tok[CAP];
    int   kk[CAP];
    float dd[CAP];
};

// smem segment sizes (bytes)
#define SC_BYTES   (MTOK * SCP * 2)            // 66048
#define BS_BYTES   ((EDIM/2) * BPITCH * 4)     // 17408
#define RES_BYTES  (MTOK * RPITCH * 4)         // 8704
#define C2S_BYTES  (GTW * 4)                   // 512
#define CAND_BYTES (NWARP * (int)sizeof(Cand)) // 8*592 = 4736
#define R2S_BYTES  (MTOK * 4)
#define SEL_BYTES  (MTOK * 4)
#define HIST_BYTES (NCODE * MTOK * 4)
#define SMEM_BYTES (SC_BYTES + BS_BYTES + RES_BYTES + C2S_BYTES + CAND_BYTES + \
                    R2S_BYTES + SEL_BYTES + HIST_BYTES)   // ~98.7KB -> 2 CTAs/SM

__global__ __launch_bounds__(TPB, 2)
void rvq_kernel(const float* __restrict__ emb,
                const float* __restrict__ cb,
                float* __restrict__ out)
{
    extern __shared__ char smem[];
    __half*   sc   = (__half*)smem;                        // [32][SCP]
    unsigned* bsw  = (unsigned*)(smem + SC_BYTES);         // [32][BPITCH]
    float*    res  = (float*)(smem + SC_BYTES + BS_BYTES); // [32][RPITCH]
    float*    c2s  = (float*)(smem + SC_BYTES + BS_BYTES + RES_BYTES);
    Cand*     cands= (Cand*)(smem + SC_BYTES + BS_BYTES + RES_BYTES + C2S_BYTES);
    float*    r2s  = (float*)((char*)cands + CAND_BYTES);
    int*      sel  = (int*)((char*)r2s + R2S_BYTES);
    int*      hist = (int*)((char*)sel + SEL_BYTES);       // [s][tok]

    const int tid  = threadIdx.x;
    const int w    = tid >> 5;      // 0..7 (= n-slice, 16 wide)
    const int lane = tid & 31;
    const int qr   = lane >> 2;     // 0..7
    const int qc   = lane & 3;      // 0..3

    // ---- init: load embeddings into res smem ----
    {
        const int tok = tid & 31;
        const int ec  = tid >> 5;       // 0..7
        const int n   = blockIdx.x * MTOK + tok;
        const int b   = n >> 12;
        const int hw  = n & 4095;
        const float* ep = emb + (size_t)b * (EDIM * 4096) + hw;
#pragma unroll
        for (int j = 0; j < 8; j++) {
            int e = ec * 8 + j;
            res[tok * RPITCH + e] = ep[(size_t)e * 4096];
        }
    }
    __syncthreads();

#pragma unroll 1
    for (int s = 0; s < NCODE; s++) {
        // ---- A fragments: BOTH m-tiles (32 tokens), bf16 packed, 32 regs
        unsigned a[2][16];
#pragma unroll
        for (int mtl = 0; mtl < 2; mtl++) {
            int r0 = mtl * 16 + qr;
            const float* p0 = res + (size_t)r0 * RPITCH;
            const float* p1 = p0 + 8 * RPITCH;
#pragma unroll
            for (int ks = 0; ks < 4; ks++) {
                int c = 16 * ks + 2 * qc;
                a[mtl][ks*4+0] = packbf(p0[c],   p0[c+1]);
                a[mtl][ks*4+1] = packbf(p1[c],   p1[c+1]);
                a[mtl][ks*4+2] = packbf(p0[c+8], p0[c+9]);
                a[mtl][ks*4+3] = packbf(p1[c+8], p1[c+9]);
            }
        }
        // ---- exact r2 per token (sequential, e ascending) ----
        if (tid < MTOK) {
            const float* rr = res + tid * RPITCH;
            float r2 = 0.0f;
#pragma unroll
            for (int e = 0; e < EDIM; e++)
                r2 = __fadd_rn(r2, __fmul_rn(rr[e], rr[e]));
            r2s[tid] = r2;
        }

        // ---- score pass over K in 8 gtiles of 128 ----
#pragma unroll 1
        for (int gt = 0; gt < NGT; gt++) {
            __syncthreads();
            // load packed B gtile into [e2][BPITCH]
            const unsigned* gsrc = g_cbt + ((size_t)s * (EDIM/2)) * KCB + gt * GTW;
#pragma unroll
            for (int j = 0; j < 4; j++) {
                int idx = j * TPB + tid;       // 0..1023
                int e2  = idx >> 5;            // 0..31
                int c4  = idx & 31;            // 0..31
                uint4 v = __ldg((const uint4*)(gsrc + (size_t)e2 * KCB) + c4);
                *(uint4*)(bsw + e2 * BPITCH + c4 * 4) = v;
            }
            if (tid < GTW)
                c2s[tid] = __ldg(g_cb2 + s * KCB + gt * GTW + tid);
            __syncthreads();

            // this warp: 16-wide n-slice, both m-tiles
            const int n0 = w * 16;
            {
                float acc[2][8];
#pragma unroll
                for (int mtl = 0; mtl < 2; mtl++)
#pragma unroll
                    for (int j = 0; j < 8; j++) acc[mtl][j] = 0.0f;

                const unsigned* bp = bsw + n0 + qr;
#pragma unroll
                for (int ks = 0; ks < 4; ks++) {
                    // conflict-free: bank = 8*qc + qr + 16w (mod 32)
                    unsigned b00 = bp[(ks*8     + qc) * BPITCH];
                    unsigned b01 = bp[(ks*8 + 4 + qc) * BPITCH];
                    unsigned b10 = bp[(ks*8     + qc) * BPITCH + 8];
                    unsigned b11 = bp[(ks*8 + 4 + qc) * BPITCH + 8];
#pragma unroll
                    for (int mtl = 0; mtl < 2; mtl++) {
                        mma_bf16(acc[mtl][0], acc[mtl][1], acc[mtl][2], acc[mtl][3],
                                 a[mtl][ks*4], a[mtl][ks*4+1], a[mtl][ks*4+2], a[mtl][ks*4+3],
                                 b00, b01);
                        mma_bf16(acc[mtl][4], acc[mtl][5], acc[mtl][6], acc[mtl][7],
                                 a[mtl][ks*4], a[mtl][ks*4+1], a[mtl][ks*4+2], a[mtl][ks*4+3],
                                 b10, b11);
                    }
                }
                // epilogue: t = cb2 - 2*dot -> fp16 scores (identical to R6)
                const int cc0 = n0 + 2*qc;
                const int cc1 = cc0 + 8;
                float2 z0 = *(const float2*)(c2s + cc0);
                float2 z1 = *(const float2*)(c2s + cc1);
                const int g0 = gt * GTW + cc0;
                const int g1 = gt * GTW + cc1;
#pragma unroll
                for (int mtl = 0; mtl < 2; mtl++) {
                    int row0 = mtl * 16 + qr, row1 = row0 + 8;
                    __half2 h00 = __halves2half2(__float2half_rn(fmaf(-2.f, acc[mtl][0], z0.x)),
                                                 __float2half_rn(fmaf(-2.f, acc[mtl][1], z0.y)));
                    __half2 h01 = __halves2half2(__float2half_rn(fmaf(-2.f, acc[mtl][2], z0.x)),
                                                 __float2half_rn(fmaf(-2.f, acc[mtl][3], z0.y)));
                    __half2 h10 = __halves2half2(__float2half_rn(fmaf(-2.f, acc[mtl][4], z1.x)),
                                                 __float2half_rn(fmaf(-2.f, acc[mtl][5], z1.y)));
                    __half2 h11 = __halves2half2(__float2half_rn(fmaf(-2.f, acc[mtl][6], z1.x)),
                                                 __float2half_rn(fmaf(-2.f, acc[mtl][7], z1.y)));
                    *(__half2*)(sc + row0 * SCP + g0) = h00;
                    *(__half2*)(sc + row1 * SCP + g0) = h01;
                    *(__half2*)(sc + row0 * SCP + g1) = h10;
                    *(__half2*)(sc + row1 * SCP + g1) = h11;
                }
            }
        }
        __syncthreads();   // scores complete

        // ---- per-warp verify: tokens w*4 .. w*4+3 (identical to R6) ----
        Cand* cd = cands + w;
        if (lane == 0) cd->cnt = 0;
        __syncwarp();
        const int tbase = w * 4;
#pragma unroll 1
        for (int t4 = 0; t4 < 4; t4++) {
            const char* srow = (const char*)(sc + (tbase + t4) * SCP);
            uint4 v[4];
            __half2 bmin[4];                 // per-uint4 block min (8 halves)
            __half2 m = __halves2half2(__half(65504.f), __half(65504.f));
#pragma unroll
            for (int jj = 0; jj < 4; jj++) {
                v[jj] = *(const uint4*)(srow + jj*512 + lane*16);
                __half2 m0 = __hmin2(u2h2(v[jj].x), u2h2(v[jj].y));
                __half2 m1 = __hmin2(u2h2(v[jj].z), u2h2(v[jj].w));
                bmin[jj] = __hmin2(m0, m1);
                m = __hmin2(m, bmin[jj]);
            }
            float lmin = __half2float(__hmin(__low2half(m), __high2half(m)));
#pragma unroll
            for (int off = 16; off; off >>= 1)
                lmin = fminf(lmin, __shfl_xor_sync(0xffffffffu, lmin, off));
            const float thr = lmin + MARGIN;
#pragma unroll
            for (int jj = 0; jj < 4; jj++) {
                float bm = __half2float(__hmin(__low2half(bmin[jj]), __high2half(bmin[jj])));
                if (bm <= thr) {           // rare: fine-scan this 8-wide block
                    int kb = jj*256 + lane*8;
                    unsigned uu[4] = {v[jj].x, v[jj].y, v[jj].z, v[jj].w};
#pragma unroll
                    for (int mm = 0; mm < 4; mm++) {
                        __half2 h = u2h2(uu[mm]);
                        if (__half2float(__low2half(h)) <= thr) {
                            int p = atomicAdd(&cd->cnt, 1);
                            if (p < CAP) { cd->tok[p] = t4; cd->kk[p] = kb + 2*mm; }
                        }
                        if (__half2float(__high2half(h)) <= thr) {
                            int p = atomicAdd(&cd->cnt, 1);
                            if (p < CAP) { cd->tok[p] = t4; cd->kk[p] = kb + 2*mm + 1; }
                        }
                    }
                }
            }
        }
        __syncwarp();
        int ncand = min(cd->cnt, CAP);
        // parallel exact evaluation of all candidates (reference numerics)
        for (int base = 0; base < ncand; base += 32) {
            int i = base + lane;
            if (i < ncand) {
                int t4 = cd->tok[i];
                int k  = cd->kk[i];
                int tok = tbase + t4;
                const float4* q4 = (const float4*)(cb + ((size_t)(s * KCB + k)) * EDIM);
                const float* rr = res + tok * RPITCH;
                float dot = 0.0f;
#pragma unroll
                for (int ii = 0; ii < 16; ii++) {
                    float4 q = __ldg(q4 + ii);
                    dot = __fmaf_rn(rr[4*ii+0], q.x, dot);
                    dot = __fmaf_rn(rr[4*ii+1], q.y, dot);
                    dot = __fmaf_rn(rr[4*ii+2], q.z, dot);
                    dot = __fmaf_rn(rr[4*ii+3], q.w, dot);
                }
                float cb2 = __ldg(g_cb2 + s * KCB + k);
                cd->dd[i] = __fadd_rn(__fsub_rn(r2s[tok], __fmul_rn(2.0f, dot)), cb2);
            }
        }
        __syncwarp();
        // per-token select with first-index tie-break
        if (lane < 4) {
            float bd = FLT_MAX; int bk = KCB;
            for (int i = 0; i < ncand; i++) {
                if (cd->tok[i] == lane) {
                    float d = cd->dd[i]; int k = cd->kk[i];
                    if (d < bd || (d == bd && k < bk)) { bd = d; bk = k; }
                }
            }
            sel[tbase + lane] = bk;
        }
        __syncthreads();

        // ---- residual update (exact) ----
        {
            int tok  = tid >> 3;           // 0..31
            int part = tid & 7;            // 0..7, 8 floats each
            int k    = sel[tok];
            const float4* qp = (const float4*)(cb + ((size_t)(s * KCB + k)) * EDIM) + part * 2;
            float* rr = res + tok * RPITCH + part * 8;
#pragma unroll
            for (int ii = 0; ii < 2; ii++) {
                float4 q  = __ldg(qp + ii);
                float4 rv = *(float4*)(rr + 4*ii);
                rv.x = __fsub_rn(rv.x, q.x);
                rv.y = __fsub_rn(rv.y, q.y);
                rv.z = __fsub_rn(rv.z, q.z);
                rv.w = __fsub_rn(rv.w, q.w);
                *(float4*)(rr + 4*ii) = rv;
            }
            if (part == 0) hist[s * MTOK + tok] = k;
        }
        __syncthreads();
    }

    // ---- final epilogue: quant = ((q0+q1)+q2)...+q7, exact order ----
    {
        const int tok = tid & 31;
        const int ec  = tid >> 5;          // 0..7
        const int e0  = ec * 8;
        const int n   = blockIdx.x * MTOK + tok;
        const int b   = n >> 12;
        const int hw  = n & 4095;

        float4 acc[2];
        {
            int k = hist[0 * MTOK + tok];
            const float4* qp = (const float4*)(cb + ((size_t)(0 * KCB + k)) * EDIM + e0);
#pragma unroll
            for (int ii = 0; ii < 2; ii++) acc[ii] = __ldg(qp + ii);
        }
#pragma unroll
        for (int s = 1; s < NCODE; s++) {
            int k = hist[s * MTOK + tok];
            const float4* qp = (const float4*)(cb + ((size_t)(s * KCB + k)) * EDIM + e0);
#pragma unroll
            for (int ii = 0; ii < 2; ii++) {
                float4 q = __ldg(qp + ii);
                acc[ii].x = __fadd_rn(acc[ii].x, q.x);
                acc[ii].y = __fadd_rn(acc[ii].y, q.y);
                acc[ii].z = __fadd_rn(acc[ii].z, q.z);
                acc[ii].w = __fadd_rn(acc[ii].w, q.w);
            }
        }
        float* op = out + (size_t)b * (EDIM * 4096) + hw;
#pragma unroll
        for (int ii = 0; ii < 2; ii++) {
            op[(size_t)(e0 + 4*ii + 0) * 4096] = acc[ii].x;
            op[(size_t)(e0 + 4*ii + 1) * 4096] = acc[ii].y;
            op[(size_t)(e0 + 4*ii + 2) * 4096] = acc[ii].z;
            op[(size_t)(e0 + 4*ii + 3) * 4096] = acc[ii].w;
        }
    }
}

extern "C" void kernel_launch(void* const* d_in, const int* in_sizes, int n_in,
                              void* d_out, int out_size)
{
    const float* emb = (const float*)d_in[0];   // [16,64,64,64]
    const float* cb  = (const float*)d_in[1];   // [8,1024,64]
    float* out = (float*)d_out;
    (void)in_sizes; (void)n_in; (void)out_size;

    cudaFuncSetAttribute(rvq_kernel, cudaFuncAttributeMaxDynamicSharedMemorySize,
                         SMEM_BYTES);

    cbt_kernel<<<dim3(32, 2, 8), dim3(32, 8)>>>(cb);
    cb2_kernel<<<(NCODE * KCB) / 256, 256>>>(cb);
    rvq_kernel<<<NTOK / MTOK, TPB, SMEM_BYTES>>>(emb, cb, out);
}